// round 8
// baseline (speedup 1.0000x reference)
#include <cuda_runtime.h>
#include <stdint.h>

#define BDIM    256                 // batch rows
#define SDIM    2048                // sequence positions
#define VDIM    128000              // vocab
#define SEGS    16                  // segments per row
#define SEGF    (VDIM / SEGS)       // 8000 floats per segment
#define THREADS 256
#define PER     (SDIM / THREADS)    // 8 positions per thread
#define NWARPS  (THREADS / 32)      // 8
#define HSEG    1024                // smem hash slots (in-segment tokens ~128)

__device__ __forceinline__ float block_reduce_max(float v, float* red) {
    __syncthreads();
    #pragma unroll
    for (int o = 16; o; o >>= 1)
        v = fmaxf(v, __shfl_xor_sync(0xffffffffu, v, o));
    int w = threadIdx.x >> 5, l = threadIdx.x & 31;
    if (l == 0) red[w] = v;
    __syncthreads();
    if (w == 0) {
        v = (l < NWARPS) ? red[l] : -1e30f;
        #pragma unroll
        for (int o = 4; o; o >>= 1)
            v = fmaxf(v, __shfl_xor_sync(0xffffffffu, v, o));
        if (l == 0) red[0] = v;
    }
    __syncthreads();
    return red[0];
}

__device__ __forceinline__ float block_reduce_sum(float v, float* red) {
    __syncthreads();
    #pragma unroll
    for (int o = 16; o; o >>= 1)
        v += __shfl_xor_sync(0xffffffffu, v, o);
    int w = threadIdx.x >> 5, l = threadIdx.x & 31;
    if (l == 0) red[w] = v;
    __syncthreads();
    if (w == 0) {
        v = (l < NWARPS) ? red[l] : 0.0f;
        #pragma unroll
        for (int o = 4; o; o >>= 1)
            v += __shfl_xor_sync(0xffffffffu, v, o);
        if (l == 0) red[0] = v;
    }
    __syncthreads();
    return red[0];
}

// One CTA = one 8000-float segment of one row. Pure zero-stream fill, then
// sparse winner overwrite into L2-hot lines (ordered by __syncthreads).
__global__ __launch_bounds__(THREADS)
void ohwa_fused2_kernel(const float* __restrict__ w_es,
                        const int* __restrict__ x32,   // raw int32 view of x
                        float* __restrict__ out,
                        long long out_elems) {
    const int s = blockIdx.x;          // segment
    const int b = blockIdx.y;          // row
    const int t = threadIdx.x;

    // dtype sniff: int64 little-endian high words are 0 for v < 2^31
    const bool is64 = (x32[1] | x32[3] | x32[5] | x32[7]) == 0;
    const int stride = is64 ? 2 : 1;
    const int* __restrict__ xrow = x32 + (size_t)b * SDIM * stride;
    const float* __restrict__ wrow = w_es + (size_t)b * SDIM;

    __shared__ int   h_key[HSEG];
    __shared__ int   h_pos[HSEG];
    __shared__ float red[NWARPS];

    // --- init hash ---
    #pragma unroll
    for (int i = t; i < HSEG; i += THREADS) {
        h_key[i] = -1;
        h_pos[i] = -1;
    }
    // (first block_reduce starts with __syncthreads(), covering init)

    // --- softmax over the row (redundant per segment; row is L2-hot) ---
    float e[PER];
    float m = -1e30f;
    #pragma unroll
    for (int j = 0; j < PER; j++) {
        e[j] = wrow[t + j * THREADS];
        m = fmaxf(m, e[j]);
    }
    m = block_reduce_max(m, red);
    float sum = 0.0f;
    #pragma unroll
    for (int j = 0; j < PER; j++) {
        e[j] = __expf(e[j] - m);
        sum += e[j];
    }
    sum = block_reduce_sum(sum, red);
    const float inv = __frcp_rn(sum);
    #pragma unroll
    for (int j = 0; j < PER; j++)
        e[j] *= inv;                   // e[j] is now the weight of pos t+j*THREADS

    // --- dedup in-segment tokens (last position wins) via small hash ---
    const int segbase = s * SEGF;
    int vv[PER];
    int slot[PER];
    #pragma unroll
    for (int j = 0; j < PER; j++) {
        int i = t + j * THREADS;
        int v = xrow[i * stride];      // low word either way (LE)
        vv[j] = v;
        unsigned off = (unsigned)(v - segbase);
        if (off >= (unsigned)SEGF) { slot[j] = -1; continue; }
        unsigned sl = (off * 2654435761u) & (HSEG - 1);
        while (true) {
            int k = h_key[sl];
            if (k == v) break;
            if (k == -1) {
                int old = atomicCAS(&h_key[sl], -1, v);
                if (old == -1 || old == v) break;
            }
            sl = (sl + 1) & (HSEG - 1);
        }
        slot[j] = (int)sl;
        atomicMax(&h_pos[sl], i);
    }

    // --- pure zero stream: the dominant, now branch-free, store loop ---
    float4* __restrict__ dst =
        reinterpret_cast<float4*>(out + (size_t)b * VDIM + segbase);
    const float4 z4 = make_float4(0.f, 0.f, 0.f, 0.f);
    #pragma unroll 4
    for (int i = t; i < SEGF / 4; i += THREADS)
        dst[i] = z4;

    __syncthreads();   // orders zero-fill stores before winner overwrites

    // --- sparse winner overwrite (lines are L2-hot from the fill above) ---
    #pragma unroll
    for (int j = 0; j < PER; j++) {
        int i = t + j * THREADS;
        if (slot[j] >= 0 && h_pos[slot[j]] == i)
            out[(size_t)b * VDIM + vv[j]] = e[j];
    }

    // --- weights output (segment 0 only) ---
    if (s == 0) {
        long long wbase = (long long)BDIM * VDIM + (long long)b * SDIM;
        #pragma unroll
        for (int j = 0; j < PER; j++) {
            long long o = wbase + t + j * THREADS;
            if (o < out_elems) out[o] = e[j];
        }
    }
}

extern "C" void kernel_launch(void* const* d_in, const int* in_sizes, int n_in,
                              void* d_out, int out_size) {
    const float* w_es = (const float*)d_in[0];
    const int*   x32  = (const int*)d_in[1];
    float*       out  = (float*)d_out;
    (void)in_sizes; (void)n_in;
    dim3 grid(SEGS, BDIM);
    ohwa_fused2_kernel<<<grid, THREADS>>>(w_es, x32, out, (long long)out_size);
}

// round 9
// speedup vs baseline: 1.0263x; 1.0263x over previous
#include <cuda_runtime.h>
#include <stdint.h>

#define BDIM    256                 // batch rows
#define SDIM    2048                // sequence positions
#define VDIM    128000              // vocab
#define SEGS    16                  // segments per row
#define SEGF    (VDIM / SEGS)       // 8000 floats per segment
#define THREADS 256
#define PER     (SDIM / THREADS)    // 8 positions per thread
#define NWARPS  (THREADS / 32)      // 8

__device__ __forceinline__ float block_reduce_max(float v, float* red) {
    __syncthreads();
    #pragma unroll
    for (int o = 16; o; o >>= 1)
        v = fmaxf(v, __shfl_xor_sync(0xffffffffu, v, o));
    int w = threadIdx.x >> 5, l = threadIdx.x & 31;
    if (l == 0) red[w] = v;
    __syncthreads();
    if (w == 0) {
        v = (l < NWARPS) ? red[l] : -1e30f;
        #pragma unroll
        for (int o = 4; o; o >>= 1)
            v = fmaxf(v, __shfl_xor_sync(0xffffffffu, v, o));
        if (l == 0) red[0] = v;
    }
    __syncthreads();
    return red[0];
}

__device__ __forceinline__ float block_reduce_sum(float v, float* red) {
    __syncthreads();
    #pragma unroll
    for (int o = 16; o; o >>= 1)
        v += __shfl_xor_sync(0xffffffffu, v, o);
    int w = threadIdx.x >> 5, l = threadIdx.x & 31;
    if (l == 0) red[w] = v;
    __syncthreads();
    if (w == 0) {
        v = (l < NWARPS) ? red[l] : 0.0f;
        #pragma unroll
        for (int o = 4; o; o >>= 1)
            v += __shfl_xor_sync(0xffffffffu, v, o);
        if (l == 0) red[0] = v;
    }
    __syncthreads();
    return red[0];
}

// One CTA = one 8000-float segment of one row. Single-touch output:
// smem seg[] holds -1 (empty) or final float bits; fill loop is
// LDS.128 -> branch-free select -> STG.128.
__global__ __launch_bounds__(THREADS)
void ohwa_fused3_kernel(const float* __restrict__ w_es,
                        const int* __restrict__ x32,   // raw int32 view of x
                        float* __restrict__ out,
                        long long out_elems) {
    const int s = blockIdx.x;          // segment
    const int b = blockIdx.y;          // row
    const int t = threadIdx.x;

    // dtype sniff: int64 little-endian high words are 0 for v < 2^31
    const bool is64 = (x32[1] | x32[3] | x32[5] | x32[7]) == 0;
    const int stride = is64 ? 2 : 1;
    const int* __restrict__ xrow = x32 + (size_t)b * SDIM * stride;
    const float* __restrict__ wrow = w_es + (size_t)b * SDIM;

    __shared__ int   seg[SEGF];        // -1 | winning position | float bits
    __shared__ float red[NWARPS];

    // --- init seg to -1 (vectorized STS.128) ---
    int4* seg4 = reinterpret_cast<int4*>(seg);
    #pragma unroll 4
    for (int i = t; i < SEGF / 4; i += THREADS)
        seg4[i] = make_int4(-1, -1, -1, -1);

    // --- softmax over the row (redundant per segment; row is L2-hot) ---
    float e[PER];
    float m = -1e30f;
    #pragma unroll
    for (int j = 0; j < PER; j++) {
        e[j] = wrow[t + j * THREADS];
        m = fmaxf(m, e[j]);
    }
    m = block_reduce_max(m, red);      // leading __syncthreads covers seg init
    float sum = 0.0f;
    #pragma unroll
    for (int j = 0; j < PER; j++) {
        e[j] = __expf(e[j] - m);
        sum += e[j];
    }
    sum = block_reduce_sum(sum, red);
    const float inv = __frcp_rn(sum);
    #pragma unroll
    for (int j = 0; j < PER; j++)
        e[j] *= inv;                   // weight of position t + j*THREADS

    // --- Phase A: last-position-wins dedup via atomicMax on positions ---
    const int segbase = s * SEGF;
    unsigned off[PER];
    #pragma unroll
    for (int j = 0; j < PER; j++) {
        int i = t + j * THREADS;
        int v = xrow[i * stride];      // low word either way (LE)
        off[j] = (unsigned)(v - segbase);
        if (off[j] < (unsigned)SEGF)
            atomicMax(&seg[off[j]], i);
    }
    __syncthreads();

    // --- Phase B: unique winner replaces its position with float bits.
    //     Softmax weights have int bit patterns >> 2047, so they are
    //     distinguishable from positions and from -1. ---
    #pragma unroll
    for (int j = 0; j < PER; j++) {
        int i = t + j * THREADS;
        if (off[j] < (unsigned)SEGF && seg[off[j]] == i)
            seg[off[j]] = __float_as_int(e[j]);
    }
    __syncthreads();

    // --- Phase C: branch-free streaming fill, one touch per output byte ---
    float4* __restrict__ dst =
        reinterpret_cast<float4*>(out + (size_t)b * VDIM + segbase);
    const int4* __restrict__ p4 = reinterpret_cast<const int4*>(seg);
    #pragma unroll 4
    for (int i = t; i < SEGF / 4; i += THREADS) {
        int4 p = p4[i];
        float4 v;
        v.x = (p.x < 0) ? 0.0f : __int_as_float(p.x);
        v.y = (p.y < 0) ? 0.0f : __int_as_float(p.y);
        v.z = (p.z < 0) ? 0.0f : __int_as_float(p.z);
        v.w = (p.w < 0) ? 0.0f : __int_as_float(p.w);
        dst[i] = v;
    }

    // --- weights output (segment 0 only) ---
    if (s == 0) {
        long long wbase = (long long)BDIM * VDIM + (long long)b * SDIM;
        #pragma unroll
        for (int j = 0; j < PER; j++) {
            long long o = wbase + t + j * THREADS;
            if (o < out_elems) out[o] = e[j];
        }
    }
}

extern "C" void kernel_launch(void* const* d_in, const int* in_sizes, int n_in,
                              void* d_out, int out_size) {
    const float* w_es = (const float*)d_in[0];
    const int*   x32  = (const int*)d_in[1];
    float*       out  = (float*)d_out;
    (void)in_sizes; (void)n_in;
    dim3 grid(SEGS, BDIM);
    ohwa_fused3_kernel<<<grid, THREADS>>>(w_es, x32, out, (long long)out_size);
}

// round 11
// speedup vs baseline: 1.1577x; 1.1281x over previous
#include <cuda_runtime.h>
#include <stdint.h>

#define BDIM    256                 // batch rows
#define SDIM    2048                // sequence positions
#define VDIM    128000              // vocab
#define SEGS    4                   // quarters per row
#define SEGF    (VDIM / SEGS)       // 32000 floats per quarter
#define THREADS 512
#define PER     (SDIM / THREADS)    // 4 positions per thread
#define HSIZE   4096                // smem hash slots for 2048 tokens
#define NWARPS  (THREADS / 32)      // 16

__device__ __forceinline__ float block_reduce_max(float v, float* red) {
    __syncthreads();
    #pragma unroll
    for (int o = 16; o; o >>= 1)
        v = fmaxf(v, __shfl_xor_sync(0xffffffffu, v, o));
    int w = threadIdx.x >> 5, l = threadIdx.x & 31;
    if (l == 0) red[w] = v;
    __syncthreads();
    if (w == 0) {
        v = (l < NWARPS) ? red[l] : -1e30f;
        #pragma unroll
        for (int o = 8; o; o >>= 1)
            v = fmaxf(v, __shfl_xor_sync(0xffffffffu, v, o));
        if (l == 0) red[0] = v;
    }
    __syncthreads();
    return red[0];
}

__device__ __forceinline__ float block_reduce_sum(float v, float* red) {
    __syncthreads();
    #pragma unroll
    for (int o = 16; o; o >>= 1)
        v += __shfl_xor_sync(0xffffffffu, v, o);
    int w = threadIdx.x >> 5, l = threadIdx.x & 31;
    if (l == 0) red[w] = v;
    __syncthreads();
    if (w == 0) {
        v = (l < NWARPS) ? red[l] : 0.0f;
        #pragma unroll
        for (int o = 8; o; o >>= 1)
            v += __shfl_xor_sync(0xffffffffu, v, o);
        if (l == 0) red[0] = v;
    }
    __syncthreads();
    return red[0];
}

// One CTA = one quarter of one row's w_a. Memset-like pure zero stream
// (no smem in the loop), then ~32 winner overwrites into L2-hot lines.
__global__ __launch_bounds__(THREADS)
void ohwa_q_kernel(const float* __restrict__ w_es,
                   const int* __restrict__ x32,   // raw int32 view of x
                   float* __restrict__ out,
                   long long out_elems) {
    const int s = blockIdx.x;          // quarter
    const int b = blockIdx.y;          // row
    const int t = threadIdx.x;

    // dtype sniff: int64 little-endian high words are 0 for v < 2^31
    const bool is64 = (x32[1] | x32[3] | x32[5] | x32[7]) == 0;
    const int stride = is64 ? 2 : 1;
    const int* __restrict__ xrow = x32 + (size_t)b * SDIM * stride;
    const float* __restrict__ wrow = w_es + (size_t)b * SDIM;

    __shared__ int   h_key[HSIZE];
    __shared__ int   h_pos[HSIZE];
    __shared__ float red[NWARPS];

    // --- init hash ---
    #pragma unroll
    for (int i = t; i < HSIZE; i += THREADS) {
        h_key[i] = -1;
        h_pos[i] = -1;
    }
    // (first block_reduce begins with __syncthreads(), covering init)

    // --- softmax over the full row (redundant across 4 quarter-CTAs) ---
    float e[PER];
    float m = -1e30f;
    #pragma unroll
    for (int j = 0; j < PER; j++) {
        e[j] = wrow[t + j * THREADS];
        m = fmaxf(m, e[j]);
    }
    m = block_reduce_max(m, red);
    float sum = 0.0f;
    #pragma unroll
    for (int j = 0; j < PER; j++) {
        e[j] = __expf(e[j] - m);
        sum += e[j];
    }
    sum = block_reduce_sum(sum, red);
    const float inv = __frcp_rn(sum);
    #pragma unroll
    for (int j = 0; j < PER; j++)
        e[j] *= inv;                   // weight of position t + j*THREADS

    // --- dedup over full row: last position wins ---
    int vv[PER];
    int slot[PER];
    #pragma unroll
    for (int j = 0; j < PER; j++) {
        int i = t + j * THREADS;
        int v = xrow[i * stride];      // low word either way (LE)
        vv[j] = v;
        if ((unsigned)v >= VDIM) { slot[j] = -1; continue; }
        unsigned sl = ((unsigned)v * 2654435761u) & (HSIZE - 1);
        while (true) {
            int k = h_key[sl];
            if (k == v) break;
            if (k == -1) {
                int old = atomicCAS(&h_key[sl], -1, v);
                if (old == -1 || old == v) break;
            }
            sl = (sl + 1) & (HSIZE - 1);
        }
        slot[j] = (int)sl;
        atomicMax(&h_pos[sl], i);
    }

    // --- pure zero stream over my quarter (memset-like; no smem reads) ---
    const int segbase = s * SEGF;
    float4* __restrict__ dst =
        reinterpret_cast<float4*>(out + (size_t)b * VDIM + segbase);
    const float4 z4 = make_float4(0.f, 0.f, 0.f, 0.f);
    #pragma unroll 4
    for (int i = t; i < SEGF / 4; i += THREADS)
        dst[i] = z4;

    __syncthreads();   // orders zero stores before winner overwrites (block scope)

    // --- winner overwrites falling in my quarter (~32 per CTA, L2-hot) ---
    #pragma unroll
    for (int j = 0; j < PER; j++) {
        int i = t + j * THREADS;
        if (slot[j] >= 0 && h_pos[slot[j]] == i) {
            unsigned off = (unsigned)(vv[j] - segbase);
            if (off < (unsigned)SEGF)
                out[(size_t)b * VDIM + segbase + off] = e[j];
        }
    }

    // --- weights output (quarter 0 only) ---
    if (s == 0) {
        long long wbase = (long long)BDIM * VDIM + (long long)b * SDIM;
        #pragma unroll
        for (int j = 0; j < PER; j++) {
            long long o = wbase + t + j * THREADS;
            if (o < out_elems) out[o] = e[j];
        }
    }
}

extern "C" void kernel_launch(void* const* d_in, const int* in_sizes, int n_in,
                              void* d_out, int out_size) {
    const float* w_es = (const float*)d_in[0];
    const int*   x32  = (const int*)d_in[1];
    float*       out  = (float*)d_out;
    (void)in_sizes; (void)n_in;
    dim3 grid(SEGS, BDIM);
    ohwa_q_kernel<<<grid, THREADS>>>(w_es, x32, out, (long long)out_size);
}